// round 2
// baseline (speedup 1.0000x reference)
#include <cuda_runtime.h>

// ---------------- problem constants ----------------
#define NLOC   6400        // 80*80 query/key locations per batch
#define DH     144         // Ci*K*K = 16*9
#define NPIX   25600       // 160*160
#define CIN    64
#define CI     16
#define DD     8
#define MIDOFF (4*NPIX)    // mid = D/2 = 4

typedef unsigned long long u64;

// ---------------- packed f32x2 helpers ----------------
__device__ __forceinline__ u64 pk2(float lo, float hi){
    u64 r; asm("mov.b64 %0,{%1,%2};" : "=l"(r) : "f"(lo), "f"(hi)); return r;
}
__device__ __forceinline__ void fma2(u64 &a, u64 x, u64 y){
    asm("fma.rn.f32x2 %0,%1,%2,%0;" : "+l"(a) : "l"(x), "l"(y));
}
__device__ __forceinline__ u64 mul2(u64 x, u64 y){
    u64 r; asm("mul.rn.f32x2 %0,%1,%2;" : "=l"(r) : "l"(x), "l"(y)); return r;
}
__device__ __forceinline__ float sumhl(u64 a){
    float l, h; asm("mov.b64 {%0,%1}, %2;" : "=f"(l), "=f"(h) : "l"(a)); return l + h;
}

// ---------------- scratch (static device globals; no allocs) ----------------
__device__ float g_X[2*3*CI*NPIX];     // conv outputs at mid slice: [batch][mat(g,theta,phi)][ci][pix]
__device__ float g_Q[2*NLOC*DH];       // Q pre-scaled by 10*log2(e)
__device__ float g_K[2*NLOC*DH];
__device__ float g_V[2*NLOC*DH];
__device__ float g_Z[2*NLOC*DH];       // attention output
__device__ float g_Y[2*CIN*NPIX];      // W-conv of folded zi2 (+bias)

// ================= K1: 1x1 conv at mid slice (3 projections) =================
__global__ void conv_mid_kernel(const float* __restrict__ b,
                                const float* __restrict__ gw, const float* __restrict__ gb,
                                const float* __restrict__ tw, const float* __restrict__ tb,
                                const float* __restrict__ pw, const float* __restrict__ pb)
{
    __shared__ float ws[3*CI*CIN];
    __shared__ float bs[3*CI];
    int tid = threadIdx.x;
    for (int i = tid; i < CI*CIN; i += 256){
        ws[i] = gw[i]; ws[CI*CIN + i] = tw[i]; ws[2*CI*CIN + i] = pw[i];
    }
    if (tid < CI){ bs[tid] = gb[tid]; bs[CI+tid] = tb[tid]; bs[2*CI+tid] = pb[tid]; }
    __syncthreads();

    int pix   = blockIdx.x*256 + tid;          // 25600 = 100*256 exact
    int batch = blockIdx.y;
    const float* bp = b + (size_t)batch*CIN*DD*NPIX + MIDOFF + pix;

    float acc[48];
    #pragma unroll
    for (int i = 0; i < 48; i++) acc[i] = bs[i];

    for (int c = 0; c < CIN; c++){
        float v = bp[(size_t)c*DD*NPIX];
        #pragma unroll
        for (int m = 0; m < 3; m++)
            #pragma unroll
            for (int ci = 0; ci < CI; ci++)
                acc[m*CI + ci] += ws[m*CI*CIN + ci*CIN + c] * v;
    }
    float* xo = g_X + (size_t)batch*3*CI*NPIX;
    #pragma unroll
    for (int i = 0; i < 48; i++)
        xo[(size_t)i*NPIX + pix] = acc[i];
}

// ================= K2: unfold to patch matrices Q/K/V [6400][144] =================
__global__ void build_patches_kernel()
{
    int batch = blockIdx.z;
    int mat   = blockIdx.y;                    // 0=g->Q, 1=theta->V, 2=phi->K
    int idx   = blockIdx.x*256 + threadIdx.x;  // 921600 = 3600*256 exact
    int l = idx / DH, j = idx % DH;
    int ci = j / 9, t = j % 9, kr = t/3, kc = t%3;
    int ih = l / 80, iw = l % 80;
    int r = ih*2 + kr - 1, c = iw*2 + kc - 1;
    const float* X = g_X + ((size_t)(batch*3 + mat))*CI*NPIX;
    float v = 0.f;
    if ((unsigned)r < 160u && (unsigned)c < 160u) v = X[ci*NPIX + r*160 + c];
    float scale = (mat == 0) ? 14.4269504088896340736f : 1.0f;  // 10 * log2(e)
    float* dst = (mat == 0 ? g_Q : (mat == 1 ? g_V : g_K)) + (size_t)batch*NLOC*DH;
    dst[idx] = v * scale;
}

// ================= K3: flash attention, fp32 + packed f32x2 =================
// smem layout (floats)
#define SM_QS 0            // [64][144]
#define SM_KS 9216         // 16 groups * 578 (pair-grouped, conflict-free)
#define SM_VS 18464        // [64][144]
#define SM_PS 27680        // [64][68]
#define SM_M  32032
#define SM_L  32096
#define SM_SC 32160
#define SM_FLOATS 32224
#define SM_BYTES (SM_FLOATS*4)

__global__ __launch_bounds__(256, 1) void flash_kernel()
{
    extern __shared__ float sm[];
    int tid   = threadIdx.x;
    int batch = blockIdx.y;
    int qb    = blockIdx.x;

    const float* Qg = g_Q + (size_t)batch*NLOC*DH;
    const float* Kg = g_K + (size_t)batch*NLOC*DH;
    const float* Vg = g_V + (size_t)batch*NLOC*DH;
    float*       Zg = g_Z + (size_t)batch*NLOC*DH;

    // load Q tile (plain layout)
    {
        const float4* qsrc = (const float4*)(Qg + (size_t)qb*64*DH);
        float4* qdst = (float4*)(sm + SM_QS);
        for (int t = tid; t < 64*DH/4; t += 256) qdst[t] = qsrc[t];
    }
    if (tid < 64){ sm[SM_M + tid] = -1e30f; sm[SM_L + tid] = 0.f; }

    const int tx  = tid & 15, ty  = tid >> 4;   // S-phase: 4 rows x 4 cols each
    const int txv = tid & 7,  tyv = tid >> 3;   // PV-phase: 2 rows x 18 cols each
    const int r0 = 2*tyv, r1 = r0 + 1, cb = txv*18;

    u64 oacc[2][9];
    #pragma unroll
    for (int i = 0; i < 2; i++)
        #pragma unroll
        for (int p = 0; p < 9; p++) oacc[i][p] = 0ull;

    for (int kb = 0; kb < 100; kb++){
        if (kb) __syncthreads();     // PV of prev iter done before overwriting K/V

        // --- load V tile (plain) ---
        {
            const float4* vsrc = (const float4*)(Vg + (size_t)kb*64*DH);
            float4* vdst = (float4*)(sm + SM_VS);
            for (int t = tid; t < 64*DH/4; t += 256) vdst[t] = vsrc[t];
        }
        // --- load K tile into pair-grouped layout ---
        {
            const float4* ksrc = (const float4*)(Kg + (size_t)kb*64*DH);
            for (int t = tid; t < 64*DH/4; t += 256){
                float4 v = ksrc[t];
                int c  = (t*4)/DH, k0 = (t*4)%DH;     // k0 in {0,4,...,140}
                int g  = c >> 2,   j  = c & 3;
                float* kd = sm + SM_KS + g*578 + (((k0>>1)*4 + j) << 1);
                kd[0] = v.x; kd[1] = v.y; kd[8] = v.z; kd[9] = v.w;
            }
        }
        __syncthreads();

        // --- S = Q K^T, packed over k ---
        u64 acc[4][4];
        #pragma unroll
        for (int i = 0; i < 4; i++)
            #pragma unroll
            for (int j = 0; j < 4; j++) acc[i][j] = 0ull;

        const u64* q0 = (const u64*)(sm + SM_QS + (4*ty+0)*DH);
        const u64* q1 = (const u64*)(sm + SM_QS + (4*ty+1)*DH);
        const u64* q2 = (const u64*)(sm + SM_QS + (4*ty+2)*DH);
        const u64* q3 = (const u64*)(sm + SM_QS + (4*ty+3)*DH);
        const u64* kp = (const u64*)(sm + SM_KS + tx*578);

        #pragma unroll 4
        for (int k = 0; k < 72; k++){
            u64 qv0 = q0[k], qv1 = q1[k], qv2 = q2[k], qv3 = q3[k];
            u64 kv0 = kp[4*k+0], kv1 = kp[4*k+1], kv2 = kp[4*k+2], kv3 = kp[4*k+3];
            fma2(acc[0][0], qv0, kv0); fma2(acc[0][1], qv0, kv1);
            fma2(acc[0][2], qv0, kv2); fma2(acc[0][3], qv0, kv3);
            fma2(acc[1][0], qv1, kv0); fma2(acc[1][1], qv1, kv1);
            fma2(acc[1][2], qv1, kv2); fma2(acc[1][3], qv1, kv3);
            fma2(acc[2][0], qv2, kv0); fma2(acc[2][1], qv2, kv1);
            fma2(acc[2][2], qv2, kv2); fma2(acc[2][3], qv2, kv3);
            fma2(acc[3][0], qv3, kv0); fma2(acc[3][1], qv3, kv1);
            fma2(acc[3][2], qv3, kv2); fma2(acc[3][3], qv3, kv3);
        }

        // --- online softmax (rows 4*ty .. 4*ty+3, reduce over 16 tx lanes) ---
        #pragma unroll
        for (int i = 0; i < 4; i++){
            float s0 = sumhl(acc[i][0]), s1 = sumhl(acc[i][1]);
            float s2 = sumhl(acc[i][2]), s3 = sumhl(acc[i][3]);
            float mx = fmaxf(fmaxf(s0, s1), fmaxf(s2, s3));
            mx = fmaxf(mx, __shfl_xor_sync(0xffffffffu, mx, 1, 16));
            mx = fmaxf(mx, __shfl_xor_sync(0xffffffffu, mx, 2, 16));
            mx = fmaxf(mx, __shfl_xor_sync(0xffffffffu, mx, 4, 16));
            mx = fmaxf(mx, __shfl_xor_sync(0xffffffffu, mx, 8, 16));
            int r = 4*ty + i;
            float mo = sm[SM_M + r];
            float mn = fmaxf(mo, mx);
            float p0 = exp2f(s0 - mn), p1 = exp2f(s1 - mn);
            float p2 = exp2f(s2 - mn), p3 = exp2f(s3 - mn);
            float rs = (p0 + p1) + (p2 + p3);
            rs += __shfl_xor_sync(0xffffffffu, rs, 1, 16);
            rs += __shfl_xor_sync(0xffffffffu, rs, 2, 16);
            rs += __shfl_xor_sync(0xffffffffu, rs, 4, 16);
            rs += __shfl_xor_sync(0xffffffffu, rs, 8, 16);
            if (tx == 0){
                float sc = exp2f(mo - mn);
                sm[SM_SC + r] = sc;
                sm[SM_L  + r] = sm[SM_L + r]*sc + rs;
                sm[SM_M  + r] = mn;
            }
            ((float4*)(sm + SM_PS + r*68))[tx] = make_float4(p0, p1, p2, p3);
        }
        __syncthreads();

        // --- O = diag(sc) O + P V  (each thread: rows r0,r1; 9 col-pairs at cb) ---
        {
            float sa = sm[SM_SC + r0], sb = sm[SM_SC + r1];
            u64 sA = pk2(sa, sa), sB = pk2(sb, sb);
            #pragma unroll
            for (int p = 0; p < 9; p++){
                oacc[0][p] = mul2(oacc[0][p], sA);
                oacc[1][p] = mul2(oacc[1][p], sB);
            }
            const float* ps0 = sm + SM_PS + r0*68;
            const float* ps1 = sm + SM_PS + r1*68;
            #pragma unroll 2
            for (int c = 0; c < 64; c++){
                float pa = ps0[c], pb = ps1[c];
                u64 pA = pk2(pa, pa), pB = pk2(pb, pb);
                const u64* vr = (const u64*)(sm + SM_VS + c*DH + cb);
                #pragma unroll
                for (int p = 0; p < 9; p++){
                    u64 vv = vr[p];
                    fma2(oacc[0][p], pA, vv);
                    fma2(oacc[1][p], pB, vv);
                }
            }
        }
    }

    // --- epilogue: normalize by l and store ---
    float inv0 = 1.f / sm[SM_L + r0];
    float inv1 = 1.f / sm[SM_L + r1];
    u64 i0 = pk2(inv0, inv0), i1 = pk2(inv1, inv1);
    u64* z0 = (u64*)(Zg + (size_t)(qb*64 + r0)*DH + cb);
    u64* z1 = (u64*)(Zg + (size_t)(qb*64 + r1)*DH + cb);
    #pragma unroll
    for (int p = 0; p < 9; p++){
        z0[p] = mul2(oacc[0][p], i0);
        z1[p] = mul2(oacc[1][p], i1);
    }
}

// ================= K4: fold (overlap-add + count normalize) + W conv =================
__global__ void fold_w_kernel(const float* __restrict__ Ww, const float* __restrict__ Wb)
{
    __shared__ float ws[CIN*CI];
    __shared__ float wb[CIN];
    int tid = threadIdx.x;
    for (int i = tid; i < CIN*CI; i += 256) ws[i] = Ww[i];
    if (tid < CIN) wb[tid] = Wb[tid];
    __syncthreads();

    int pix   = blockIdx.x*256 + tid;
    int batch = blockIdx.y;
    int h = pix / 160, w = pix % 160;

    int krs[2], ihs[2], nr = 0;
    if (!(h & 1)){ krs[0] = 1; ihs[0] = h >> 1; nr = 1; }
    else {
        if (h < 159){ krs[nr] = 0; ihs[nr] = (h+1) >> 1; nr++; }
        krs[nr] = 2; ihs[nr] = (h-1) >> 1; nr++;
    }
    int kcs[2], iws[2], nc = 0;
    if (!(w & 1)){ kcs[0] = 1; iws[0] = w >> 1; nc = 1; }
    else {
        if (w < 159){ kcs[nc] = 0; iws[nc] = (w+1) >> 1; nc++; }
        kcs[nc] = 2; iws[nc] = (w-1) >> 1; nc++;
    }

    const float* Z = g_Z + (size_t)batch*NLOC*DH;
    float acc[CI];
    #pragma unroll
    for (int ci = 0; ci < CI; ci++) acc[ci] = 0.f;

    for (int a = 0; a < nr; a++)
        for (int bb = 0; bb < nc; bb++){
            int l = ihs[a]*80 + iws[bb];
            const float* zp = Z + (size_t)l*DH + krs[a]*3 + kcs[bb];
            #pragma unroll
            for (int ci = 0; ci < CI; ci++) acc[ci] += zp[ci*9];
        }
    float inv = 1.f / (float)(nr*nc);
    #pragma unroll
    for (int ci = 0; ci < CI; ci++) acc[ci] *= inv;

    float* Y = g_Y + (size_t)batch*CIN*NPIX + pix;
    #pragma unroll 4
    for (int c = 0; c < CIN; c++){
        float s = wb[c];
        #pragma unroll
        for (int ci = 0; ci < CI; ci++) s += ws[c*CI + ci]*acc[ci];
        Y[(size_t)c*NPIX] = s;
    }
}

// ================= K5: out = b + Y (broadcast over D) =================
__global__ void epilogue_kernel(const float* __restrict__ b, float* __restrict__ out)
{
    size_t i = (size_t)blockIdx.x*256 + threadIdx.x;      // float4 index, 6,553,600 total
    size_t e = i*4;
    const size_t per_batch = (size_t)CIN*DD*NPIX;
    int batch = (int)(e / per_batch);
    size_t rem  = e % per_batch;
    int c  = (int)(rem / ((size_t)DD*NPIX));
    int pix = (int)(rem % NPIX);                           // multiple of 4

    float4 bv = ((const float4*)b)[i];
    const float4* y4 = (const float4*)(g_Y + (size_t)batch*CIN*NPIX + (size_t)c*NPIX + pix);
    float4 yv = *y4;
    ((float4*)out)[i] = make_float4(bv.x + yv.x, bv.y + yv.y, bv.z + yv.z, bv.w + yv.w);
}

// ================= launch =================
extern "C" void kernel_launch(void* const* d_in, const int* in_sizes, int n_in,
                              void* d_out, int out_size)
{
    const float* b   = (const float*)d_in[0];
    const float* gw  = (const float*)d_in[1];
    const float* gb  = (const float*)d_in[2];
    const float* tw  = (const float*)d_in[3];
    const float* tb  = (const float*)d_in[4];
    const float* pw  = (const float*)d_in[5];
    const float* pb  = (const float*)d_in[6];
    const float* Ww  = (const float*)d_in[7];
    const float* Wb  = (const float*)d_in[8];
    float* out = (float*)d_out;

    cudaFuncSetAttribute(flash_kernel, cudaFuncAttributeMaxDynamicSharedMemorySize, SM_BYTES);

    conv_mid_kernel<<<dim3(100, 2), 256>>>(b, gw, gb, tw, tb, pw, pb);
    build_patches_kernel<<<dim3(3600, 3, 2), 256>>>();
    flash_kernel<<<dim3(100, 2), 256, SM_BYTES>>>();
    fold_w_kernel<<<dim3(100, 2), 256>>>(Ww, Wb);
    epilogue_kernel<<<25600, 256>>>(b, out);
}

// round 5
// speedup vs baseline: 7.2130x; 7.2130x over previous
#include <cuda_runtime.h>
#include <cuda_fp16.h>
#include <cstdint>

#define NLOC 6400
#define DH   144
#define NPIX 25600
#define CIN  64
#define CI   16
#define DD   8
#define MIDOFF (4*NPIX)

// ---------------- gmem scratch ----------------
__device__ float  g_X[2*3*CI*NPIX];
__device__ float  g_Q[2*NLOC*DH];       // fp32, pre-scaled by 10*log2(e)
__device__ __half g_Kf[2*NLOC*DH];      // fp16 [loc][dh]
__device__ __half g_Vt[2*DH*NLOC];      // fp16 transposed [dh][loc]
__device__ float  g_Z[2*NLOC*DH];
__device__ float  g_Y[2*CIN*NPIX];

// ---------------- helpers ----------------
__device__ __forceinline__ uint32_t smem_u32(const void* p){
    uint32_t a; asm("{ .reg .u64 t; cvta.to.shared.u64 t, %1; cvt.u32.u64 %0, t; }" : "=r"(a) : "l"(p));
    return a;
}
__device__ __forceinline__ float ex2(float x){
    float y; asm("ex2.approx.ftz.f32 %0, %1;" : "=f"(y) : "f"(x)); return y;
}
// pack two fp32 -> fp16x2, lo half = first arg
__device__ __forceinline__ uint32_t pkh(float lo, float hi){
    uint32_t u; asm("cvt.rn.f16x2.f32 %0, %1, %2;" : "=r"(u) : "f"(hi), "f"(lo)); return u;
}
__device__ __forceinline__ void mma16816(float* d, const uint32_t* a, const uint32_t* b, const float* c){
    asm volatile("mma.sync.aligned.m16n8k16.row.col.f32.f16.f16.f32 "
        "{%0,%1,%2,%3}, {%4,%5,%6,%7}, {%8,%9}, {%10,%11,%12,%13};"
        : "=f"(d[0]),"=f"(d[1]),"=f"(d[2]),"=f"(d[3])
        : "r"(a[0]),"r"(a[1]),"r"(a[2]),"r"(a[3]), "r"(b[0]),"r"(b[1]),
          "f"(c[0]),"f"(c[1]),"f"(c[2]),"f"(c[3]));
}
__device__ __forceinline__ void ldsm4(uint32_t* r, uint32_t addr){
    asm volatile("ldmatrix.sync.aligned.m8n8.x4.shared.b16 {%0,%1,%2,%3}, [%4];"
        : "=r"(r[0]),"=r"(r[1]),"=r"(r[2]),"=r"(r[3]) : "r"(addr));
}
__device__ __forceinline__ void cpa(uint32_t dst, const void* src){
    asm volatile("cp.async.cg.shared.global [%0], [%1], 16;" :: "r"(dst), "l"(src));
}
__device__ __forceinline__ void cp_commit(){ asm volatile("cp.async.commit_group;" ::: "memory"); }
template<int N> __device__ __forceinline__ void cp_wait(){ asm volatile("cp.async.wait_group %0;" :: "n"(N) : "memory"); }

// ================= K1: 1x1 conv at mid slice =================
__global__ void conv_mid_kernel(const float* __restrict__ b,
                                const float* __restrict__ gw, const float* __restrict__ gb,
                                const float* __restrict__ tw, const float* __restrict__ tb,
                                const float* __restrict__ pw, const float* __restrict__ pb)
{
    __shared__ float ws[3*CI*CIN];
    __shared__ float bs[3*CI];
    int tid = threadIdx.x;
    for (int i = tid; i < CI*CIN; i += 256){
        ws[i] = gw[i]; ws[CI*CIN + i] = tw[i]; ws[2*CI*CIN + i] = pw[i];
    }
    if (tid < CI){ bs[tid] = gb[tid]; bs[CI+tid] = tb[tid]; bs[2*CI+tid] = pb[tid]; }
    __syncthreads();

    int pix = blockIdx.x*256 + tid;
    int batch = blockIdx.y;
    const float* bp = b + (size_t)batch*CIN*DD*NPIX + MIDOFF + pix;
    float acc[48];
    #pragma unroll
    for (int i = 0; i < 48; i++) acc[i] = bs[i];
    for (int c = 0; c < CIN; c++){
        float v = bp[(size_t)c*DD*NPIX];
        #pragma unroll
        for (int m = 0; m < 3; m++)
            #pragma unroll
            for (int ci = 0; ci < CI; ci++)
                acc[m*CI + ci] += ws[m*CI*CIN + ci*CIN + c] * v;
    }
    float* xo = g_X + (size_t)batch*3*CI*NPIX;
    #pragma unroll
    for (int i = 0; i < 48; i++) xo[(size_t)i*NPIX + pix] = acc[i];
}

// ================= K2: unfold -> Q(fp32 scaled), Kf(fp16), Vt(fp16 transposed) ====
__global__ void build_patches_kernel()
{
    int batch = blockIdx.z;
    int mat   = blockIdx.y;                    // 0=g->Q, 1=theta->V, 2=phi->K
    int idx   = blockIdx.x*256 + threadIdx.x;  // 921600
    int l, j;
    if (mat == 1){ j = idx / NLOC; l = idx - j*NLOC; }
    else         { l = idx / DH;   j = idx - l*DH;  }
    int ci = j/9, t = j%9, kr = t/3, kc = t%3;
    int ih = l/80, iw = l%80;
    int r = ih*2 + kr - 1, c = iw*2 + kc - 1;
    const float* X = g_X + ((size_t)(batch*3 + mat))*CI*NPIX;
    float v = 0.f;
    if ((unsigned)r < 160u && (unsigned)c < 160u) v = X[ci*NPIX + r*160 + c];

    if (mat == 0){
        g_Q[(size_t)batch*NLOC*DH + idx] = v * 14.4269504088896340736f; // 10*log2(e)
    } else if (mat == 1){
        g_Vt[(size_t)batch*DH*NLOC + idx] = __float2half_rn(v);
    } else {
        g_Kf[(size_t)batch*NLOC*DH + idx] = __float2half_rn(v);
    }
}

// ================= K3: flash attention, mma.sync (HMMA) =================
#define BM   96
#define KSTR 152              // halves per K-tile row (304B, conflict-free ldsm)
#define VSTR 72               // halves per V-tile row (144B, conflict-free ldsm)
#define KTB  (64*KSTR*2)      // 19456 bytes
#define VTB  (144*VSTR*2)     // 20736 bytes
#define BUFB (KTB+VTB)        // 40192
#define SMB_FLASH (2*BUFB)    // 80384

__device__ __forceinline__ void load_tiles(uint32_t smb, int buf,
                                           const __half* Kg, const __half* Vg,
                                           int kb, int tid)
{
    uint32_t kd = smb + buf*BUFB;
    const __half* ks = Kg + (size_t)kb*64*DH;
    #pragma unroll
    for (int j = 0; j < 6; j++){
        int id = tid + j*192;
        int r = id/18, c = id - r*18;     // 64 rows x 18 chunks(16B)
        cpa(kd + r*(KSTR*2) + c*16, ks + r*DH + c*8);
    }
    uint32_t vd = smb + buf*BUFB + KTB;
    const __half* vs = Vg + kb*64;
    #pragma unroll
    for (int j = 0; j < 6; j++){
        int id = tid + j*192;
        int r = id>>3, c = id&7;          // 144 rows x 8 chunks(16B)
        cpa(vd + r*(VSTR*2) + c*16, vs + (size_t)r*NLOC + c*8);
    }
}

__global__ __launch_bounds__(192, 1) void flash_kernel()
{
    extern __shared__ char sm[];
    uint32_t smb = smem_u32(sm);
    const int tid = threadIdx.x, w = tid>>5, lane = tid&31;
    const int g = lane>>2, tig = lane&3;
    const int qb = blockIdx.x, batch = blockIdx.y;

    const float*  Qg = g_Q  + (size_t)batch*NLOC*DH;
    const __half* Kg = g_Kf + (size_t)batch*NLOC*DH;
    const __half* Vg = g_Vt + (size_t)batch*DH*NLOC;
    float*        Zg = g_Z  + (size_t)batch*NLOC*DH;

    // ---- Q fragments (hi/lo fp16 split), rows row0 and row0+8 ----
    const int row0 = qb*BM + w*16 + g;
    const int r0c = min(row0, NLOC-1), r1c = min(row0+8, NLOC-1);
    uint32_t qh[36], ql[36];
    #pragma unroll
    for (int t = 0; t < 9; t++){
        const float* p0 = Qg + (size_t)r0c*DH + t*16 + tig*2;
        const float* p1 = Qg + (size_t)r1c*DH + t*16 + tig*2;
        float2 a = *(const float2*)p0;
        float2 b = *(const float2*)p1;
        float2 c = *(const float2*)(p0 + 8);
        float2 d = *(const float2*)(p1 + 8);
        uint32_t u;
        __half2 h2;
        u = pkh(a.x, a.y); qh[4*t+0] = u; h2 = *(__half2*)&u;
        ql[4*t+0] = pkh(a.x - __low2float(h2), a.y - __high2float(h2));
        u = pkh(b.x, b.y); qh[4*t+1] = u; h2 = *(__half2*)&u;
        ql[4*t+1] = pkh(b.x - __low2float(h2), b.y - __high2float(h2));
        u = pkh(c.x, c.y); qh[4*t+2] = u; h2 = *(__half2*)&u;
        ql[4*t+2] = pkh(c.x - __low2float(h2), c.y - __high2float(h2));
        u = pkh(d.x, d.y); qh[4*t+3] = u; h2 = *(__half2*)&u;
        ql[4*t+3] = pkh(d.x - __low2float(h2), d.y - __high2float(h2));
    }

    // ldmatrix per-lane base offsets
    const int lm = lane>>3;                       // matrix id 0..3
    const int lr = lane&7;
    const int lrow = lr + ((lm&2)<<2);            // +8 for matrices 2,3
    const int lcol = (lm&1)*16;                   // +8 halves for matrices 1,3

    float oa[18][4];
    #pragma unroll
    for (int j = 0; j < 18; j++){ oa[j][0]=0.f; oa[j][1]=0.f; oa[j][2]=0.f; oa[j][3]=0.f; }
    float m0 = -1e30f, m1 = -1e30f, l0 = 0.f, l1 = 0.f;

    load_tiles(smb, 0, Kg, Vg, 0, tid); cp_commit();

    for (int t = 0; t < 100; t++){
        if (t+1 < 100){ load_tiles(smb, (t+1)&1, Kg, Vg, t+1, tid); cp_commit(); cp_wait<1>(); }
        else          { cp_wait<0>(); }
        __syncthreads();

        const uint32_t kmb = smb + (t&1)*BUFB + lrow*(KSTR*2) + lcol;
        const uint32_t vmb = smb + (t&1)*BUFB + KTB + lrow*(VSTR*2) + lcol;

        // ---- S = Qh*K + Ql*K ----
        float sa[8][4];
        #pragma unroll
        for (int j = 0; j < 8; j++){ sa[j][0]=0.f; sa[j][1]=0.f; sa[j][2]=0.f; sa[j][3]=0.f; }
        #pragma unroll
        for (int np = 0; np < 4; np++){
            #pragma unroll
            for (int kt = 0; kt < 9; kt++){
                uint32_t bb[4];
                ldsm4(bb, kmb + np*16*(KSTR*2) + kt*32);
                mma16816(sa[2*np],   &qh[4*kt], bb,   sa[2*np]);
                mma16816(sa[2*np],   &ql[4*kt], bb,   sa[2*np]);
                mma16816(sa[2*np+1], &qh[4*kt], bb+2, sa[2*np+1]);
                mma16816(sa[2*np+1], &ql[4*kt], bb+2, sa[2*np+1]);
            }
        }

        // ---- online softmax (log2 domain) ----
        float mx0 = -1e30f, mx1 = -1e30f;
        #pragma unroll
        for (int j = 0; j < 8; j++){
            mx0 = fmaxf(mx0, fmaxf(sa[j][0], sa[j][1]));
            mx1 = fmaxf(mx1, fmaxf(sa[j][2], sa[j][3]));
        }
        mx0 = fmaxf(mx0, __shfl_xor_sync(0xffffffffu, mx0, 1));
        mx0 = fmaxf(mx0, __shfl_xor_sync(0xffffffffu, mx0, 2));
        mx1 = fmaxf(mx1, __shfl_xor_sync(0xffffffffu, mx1, 1));
        mx1 = fmaxf(mx1, __shfl_xor_sync(0xffffffffu, mx1, 2));
        float m0n = fmaxf(m0, mx0), m1n = fmaxf(m1, mx1);
        float sc0 = ex2(m0 - m0n),  sc1 = ex2(m1 - m1n);
        m0 = m0n; m1 = m1n;
        float rs0 = 0.f, rs1 = 0.f;
        #pragma unroll
        for (int j = 0; j < 8; j++){
            sa[j][0] = ex2(sa[j][0] - m0); sa[j][1] = ex2(sa[j][1] - m0);
            sa[j][2] = ex2(sa[j][2] - m1); sa[j][3] = ex2(sa[j][3] - m1);
            rs0 += sa[j][0] + sa[j][1];
            rs1 += sa[j][2] + sa[j][3];
        }
        rs0 += __shfl_xor_sync(0xffffffffu, rs0, 1);
        rs0 += __shfl_xor_sync(0xffffffffu, rs0, 2);
        rs1 += __shfl_xor_sync(0xffffffffu, rs1, 1);
        rs1 += __shfl_xor_sync(0xffffffffu, rs1, 2);
        l0 = l0*sc0 + rs0;
        l1 = l1*sc1 + rs1;
        #pragma unroll
        for (int j = 0; j < 18; j++){
            oa[j][0] *= sc0; oa[j][1] *= sc0;
            oa[j][2] *= sc1; oa[j][3] *= sc1;
        }

        // ---- P fragments (A operand of PV) ----
        uint32_t pa[4][4];
        #pragma unroll
        for (int k2 = 0; k2 < 4; k2++){
            pa[k2][0] = pkh(sa[2*k2][0],   sa[2*k2][1]);
            pa[k2][1] = pkh(sa[2*k2][2],   sa[2*k2][3]);
            pa[k2][2] = pkh(sa[2*k2+1][0], sa[2*k2+1][1]);
            pa[k2][3] = pkh(sa[2*k2+1][2], sa[2*k2+1][3]);
        }

        // ---- O += P * V ----
        #pragma unroll
        for (int np = 0; np < 9; np++){
            #pragma unroll
            for (int k2 = 0; k2 < 4; k2++){
                uint32_t bb[4];
                ldsm4(bb, vmb + np*16*(VSTR*2) + k2*32);
                mma16816(oa[2*np],   pa[k2], bb,   oa[2*np]);
                mma16816(oa[2*np+1], pa[k2], bb+2, oa[2*np+1]);
            }
        }
        __syncthreads();
    }

    // ---- epilogue ----
    float i0 = 1.f/l0, i1 = 1.f/l1;
    if (row0 < NLOC){
        float* z = Zg + (size_t)row0*DH + tig*2;
        #pragma unroll
        for (int j = 0; j < 18; j++)
            *(float2*)(z + j*8) = make_float2(oa[j][0]*i0, oa[j][1]*i0);
    }
    if (row0 + 8 < NLOC){
        float* z = Zg + (size_t)(row0+8)*DH + tig*2;
        #pragma unroll
        for (int j = 0; j < 18; j++)
            *(float2*)(z + j*8) = make_float2(oa[j][2]*i1, oa[j][3]*i1);
    }
}

// ================= K4: fold + W conv =================
__global__ void fold_w_kernel(const float* __restrict__ Ww, const float* __restrict__ Wb)
{
    __shared__ float ws[CIN*CI];
    __shared__ float wb[CIN];
    int tid = threadIdx.x;
    for (int i = tid; i < CIN*CI; i += 256) ws[i] = Ww[i];
    if (tid < CIN) wb[tid] = Wb[tid];
    __syncthreads();

    int pix = blockIdx.x*256 + tid;
    int batch = blockIdx.y;
    int h = pix / 160, w = pix % 160;

    int krs[2], ihs[2], nr = 0;
    if (!(h & 1)){ krs[0] = 1; ihs[0] = h >> 1; nr = 1; }
    else { if (h < 159){ krs[nr] = 0; ihs[nr] = (h+1) >> 1; nr++; } krs[nr] = 2; ihs[nr] = (h-1) >> 1; nr++; }
    int kcs[2], iws[2], nc = 0;
    if (!(w & 1)){ kcs[0] = 1; iws[0] = w >> 1; nc = 1; }
    else { if (w < 159){ kcs[nc] = 0; iws[nc] = (w+1) >> 1; nc++; } kcs[nc] = 2; iws[nc] = (w-1) >> 1; nc++; }

    const float* Z = g_Z + (size_t)batch*NLOC*DH;
    float acc[CI];
    #pragma unroll
    for (int ci = 0; ci < CI; ci++) acc[ci] = 0.f;
    for (int a = 0; a < nr; a++)
        for (int bb = 0; bb < nc; bb++){
            int l = ihs[a]*80 + iws[bb];
            const float* zp = Z + (size_t)l*DH + krs[a]*3 + kcs[bb];
            #pragma unroll
            for (int ci = 0; ci < CI; ci++) acc[ci] += zp[ci*9];
        }
    float inv = 1.f / (float)(nr*nc);
    #pragma unroll
    for (int ci = 0; ci < CI; ci++) acc[ci] *= inv;

    float* Y = g_Y + (size_t)batch*CIN*NPIX + pix;
    #pragma unroll 4
    for (int c = 0; c < CIN; c++){
        float s = wb[c];
        #pragma unroll
        for (int ci = 0; ci < CI; ci++) s += ws[c*CI + ci]*acc[ci];
        Y[(size_t)c*NPIX] = s;
    }
}

// ================= K5: out = b + Y =================
__global__ void epilogue_kernel(const float* __restrict__ b, float* __restrict__ out)
{
    size_t i = (size_t)blockIdx.x*256 + threadIdx.x;
    size_t e = i*4;
    const size_t per_batch = (size_t)CIN*DD*NPIX;
    int batch = (int)(e / per_batch);
    size_t rem = e % per_batch;
    int c = (int)(rem / ((size_t)DD*NPIX));
    int pix = (int)(rem % NPIX);
    float4 bv = ((const float4*)b)[i];
    float4 yv = *(const float4*)(g_Y + (size_t)batch*CIN*NPIX + (size_t)c*NPIX + pix);
    ((float4*)out)[i] = make_float4(bv.x + yv.x, bv.y + yv.y, bv.z + yv.z, bv.w + yv.w);
}

// ================= launch =================
extern "C" void kernel_launch(void* const* d_in, const int* in_sizes, int n_in,
                              void* d_out, int out_size)
{
    const float* b  = (const float*)d_in[0];
    const float* gw = (const float*)d_in[1];
    const float* gb = (const float*)d_in[2];
    const float* tw = (const float*)d_in[3];
    const float* tb = (const float*)d_in[4];
    const float* pw = (const float*)d_in[5];
    const float* pb = (const float*)d_in[6];
    const float* Ww = (const float*)d_in[7];
    const float* Wb = (const float*)d_in[8];
    float* out = (float*)d_out;

    cudaFuncSetAttribute(flash_kernel, cudaFuncAttributeMaxDynamicSharedMemorySize, SMB_FLASH);

    conv_mid_kernel<<<dim3(100, 2), 256>>>(b, gw, gb, tw, tb, pw, pb);
    build_patches_kernel<<<dim3(3600, 3, 2), 256>>>();
    flash_kernel<<<dim3(67, 2), 192, SMB_FLASH>>>();
    fold_w_kernel<<<dim3(100, 2), 256>>>(Ww, Wb);
    epilogue_kernel<<<25600, 256>>>(b, out);
}

// round 6
// speedup vs baseline: 8.3529x; 1.1580x over previous
#include <cuda_runtime.h>
#include <cuda_fp16.h>
#include <cstdint>

#define NLOC 6400
#define DH   144
#define NPIX 25600
#define CIN  64
#define CI   16
#define DD   8
#define MIDOFF (4*NPIX)

// ---------------- gmem scratch ----------------
__device__ float  g_X[2*3*CI*NPIX];
__device__ float  g_Q[2*NLOC*DH];       // fp32, pre-scaled by 10*log2(e)
__device__ __half g_Kf[2*NLOC*DH];      // fp16 [loc][dh]
__device__ __half g_Vt[2*DH*NLOC];      // fp16 transposed [dh][loc]
__device__ float  g_Z[2*NLOC*DH];

// ---------------- helpers ----------------
__device__ __forceinline__ uint32_t smem_u32(const void* p){
    uint32_t a; asm("{ .reg .u64 t; cvta.to.shared.u64 t, %1; cvt.u32.u64 %0, t; }" : "=r"(a) : "l"(p));
    return a;
}
__device__ __forceinline__ float ex2(float x){
    float y; asm("ex2.approx.ftz.f32 %0, %1;" : "=f"(y) : "f"(x)); return y;
}
// pack two fp32 -> fp16x2, lo half = first arg
__device__ __forceinline__ uint32_t pkh(float lo, float hi){
    uint32_t u; asm("cvt.rn.f16x2.f32 %0, %1, %2;" : "=r"(u) : "f"(hi), "f"(lo)); return u;
}
__device__ __forceinline__ void mma16816(float* d, const uint32_t* a, const uint32_t* b, const float* c){
    asm volatile("mma.sync.aligned.m16n8k16.row.col.f32.f16.f16.f32 "
        "{%0,%1,%2,%3}, {%4,%5,%6,%7}, {%8,%9}, {%10,%11,%12,%13};"
        : "=f"(d[0]),"=f"(d[1]),"=f"(d[2]),"=f"(d[3])
        : "r"(a[0]),"r"(a[1]),"r"(a[2]),"r"(a[3]), "r"(b[0]),"r"(b[1]),
          "f"(c[0]),"f"(c[1]),"f"(c[2]),"f"(c[3]));
}
__device__ __forceinline__ void ldsm4(uint32_t* r, uint32_t addr){
    asm volatile("ldmatrix.sync.aligned.m8n8.x4.shared.b16 {%0,%1,%2,%3}, [%4];"
        : "=r"(r[0]),"=r"(r[1]),"=r"(r[2]),"=r"(r[3]) : "r"(addr));
}
__device__ __forceinline__ void cpa(uint32_t dst, const void* src){
    asm volatile("cp.async.cg.shared.global [%0], [%1], 16;" :: "r"(dst), "l"(src));
}
__device__ __forceinline__ void cp_commit(){ asm volatile("cp.async.commit_group;" ::: "memory"); }
template<int N> __device__ __forceinline__ void cp_wait(){ asm volatile("cp.async.wait_group %0;" :: "n"(N) : "memory"); }

// ================= K1: 1x1 conv at mid slice =================
__global__ void conv_mid_kernel(const float* __restrict__ b,
                                const float* __restrict__ gw, const float* __restrict__ gb,
                                const float* __restrict__ tw, const float* __restrict__ tb,
                                const float* __restrict__ pw, const float* __restrict__ pb)
{
    __shared__ float ws[3*CI*CIN];
    __shared__ float bs[3*CI];
    int tid = threadIdx.x;
    for (int i = tid; i < CI*CIN; i += 256){
        ws[i] = gw[i]; ws[CI*CIN + i] = tw[i]; ws[2*CI*CIN + i] = pw[i];
    }
    if (tid < CI){ bs[tid] = gb[tid]; bs[CI+tid] = tb[tid]; bs[2*CI+tid] = pb[tid]; }
    __syncthreads();

    int pix = blockIdx.x*256 + tid;
    int batch = blockIdx.y;
    const float* bp = b + (size_t)batch*CIN*DD*NPIX + MIDOFF + pix;
    float acc[48];
    #pragma unroll
    for (int i = 0; i < 48; i++) acc[i] = bs[i];
    for (int c = 0; c < CIN; c++){
        float v = bp[(size_t)c*DD*NPIX];
        #pragma unroll
        for (int m = 0; m < 3; m++)
            #pragma unroll
            for (int ci = 0; ci < CI; ci++)
                acc[m*CI + ci] += ws[m*CI*CIN + ci*CIN + c] * v;
    }
    float* xo = g_X + (size_t)batch*3*CI*NPIX;
    #pragma unroll
    for (int i = 0; i < 48; i++) xo[(size_t)i*NPIX + pix] = acc[i];
}

// ================= K2: unfold -> Q(fp32 scaled), Kf(fp16), Vt(fp16 transposed) ====
__global__ void build_patches_kernel()
{
    int batch = blockIdx.z;
    int mat   = blockIdx.y;                    // 0=g->Q, 1=theta->V, 2=phi->K
    int idx   = blockIdx.x*256 + threadIdx.x;  // 921600
    int l, j;
    if (mat == 1){ j = idx / NLOC; l = idx - j*NLOC; }
    else         { l = idx / DH;   j = idx - l*DH;  }
    int ci = j/9, t = j%9, kr = t/3, kc = t%3;
    int ih = l/80, iw = l%80;
    int r = ih*2 + kr - 1, c = iw*2 + kc - 1;
    const float* X = g_X + ((size_t)(batch*3 + mat))*CI*NPIX;
    float v = 0.f;
    if ((unsigned)r < 160u && (unsigned)c < 160u) v = X[ci*NPIX + r*160 + c];

    if (mat == 0){
        g_Q[(size_t)batch*NLOC*DH + idx] = v * 14.4269504088896340736f; // 10*log2(e)
    } else if (mat == 1){
        g_Vt[(size_t)batch*DH*NLOC + idx] = __float2half_rn(v);
    } else {
        g_Kf[(size_t)batch*NLOC*DH + idx] = __float2half_rn(v);
    }
}

// ================= K3: flash attention, mma.sync (HMMA) =================
#define BM   96
#define KSTR 152              // halves per K-tile row (304B, conflict-free ldsm)
#define VSTR 72               // halves per V-tile row (144B, conflict-free ldsm)
#define KTB  (64*KSTR*2)      // 19456 bytes
#define VTB  (144*VSTR*2)     // 20736 bytes
#define BUFB (KTB+VTB)        // 40192
#define SMB_FLASH (2*BUFB)    // 80384

__device__ __forceinline__ void load_tiles(uint32_t smb, int buf,
                                           const __half* Kg, const __half* Vg,
                                           int kb, int tid)
{
    uint32_t kd = smb + buf*BUFB;
    const __half* ks = Kg + (size_t)kb*64*DH;
    #pragma unroll
    for (int j = 0; j < 6; j++){
        int id = tid + j*192;
        int r = id/18, c = id - r*18;     // 64 rows x 18 chunks(16B)
        cpa(kd + r*(KSTR*2) + c*16, ks + r*DH + c*8);
    }
    uint32_t vd = smb + buf*BUFB + KTB;
    const __half* vs = Vg + kb*64;
    #pragma unroll
    for (int j = 0; j < 6; j++){
        int id = tid + j*192;
        int r = id>>3, c = id&7;          // 144 rows x 8 chunks(16B)
        cpa(vd + r*(VSTR*2) + c*16, vs + (size_t)r*NLOC + c*8);
    }
}

__global__ __launch_bounds__(192, 1) void flash_kernel()
{
    extern __shared__ char sm[];
    uint32_t smb = smem_u32(sm);
    const int tid = threadIdx.x, w = tid>>5, lane = tid&31;
    const int g = lane>>2, tig = lane&3;
    const int qb = blockIdx.x, batch = blockIdx.y;

    const float*  Qg = g_Q  + (size_t)batch*NLOC*DH;
    const __half* Kg = g_Kf + (size_t)batch*NLOC*DH;
    const __half* Vg = g_Vt + (size_t)batch*DH*NLOC;
    float*        Zg = g_Z  + (size_t)batch*NLOC*DH;

    // ---- Q fragments (fp16), rows row0 and row0+8 ----
    const int row0 = qb*BM + w*16 + g;
    const int r0c = min(row0, NLOC-1), r1c = min(row0+8, NLOC-1);
    uint32_t qh[36];
    #pragma unroll
    for (int t = 0; t < 9; t++){
        const float* p0 = Qg + (size_t)r0c*DH + t*16 + tig*2;
        const float* p1 = Qg + (size_t)r1c*DH + t*16 + tig*2;
        float2 a = *(const float2*)p0;
        float2 b = *(const float2*)p1;
        float2 c = *(const float2*)(p0 + 8);
        float2 d = *(const float2*)(p1 + 8);
        qh[4*t+0] = pkh(a.x, a.y);
        qh[4*t+1] = pkh(b.x, b.y);
        qh[4*t+2] = pkh(c.x, c.y);
        qh[4*t+3] = pkh(d.x, d.y);
    }

    // ldmatrix per-lane base offsets
    const int lm = lane>>3;                       // matrix id 0..3
    const int lr = lane&7;
    const int lrow = lr + ((lm&2)<<2);            // +8 for matrices 2,3
    const int lcol = (lm&1)*16;                   // +8 halves for matrices 1,3

    float oa[18][4];
    #pragma unroll
    for (int j = 0; j < 18; j++){ oa[j][0]=0.f; oa[j][1]=0.f; oa[j][2]=0.f; oa[j][3]=0.f; }
    float m0 = -1e30f, m1 = -1e30f, l0 = 0.f, l1 = 0.f;

    load_tiles(smb, 0, Kg, Vg, 0, tid); cp_commit();

    for (int t = 0; t < 100; t++){
        if (t+1 < 100){ load_tiles(smb, (t+1)&1, Kg, Vg, t+1, tid); cp_commit(); cp_wait<1>(); }
        else          { cp_wait<0>(); }
        __syncthreads();

        const uint32_t kmb = smb + (t&1)*BUFB + lrow*(KSTR*2) + lcol;
        const uint32_t vmb = smb + (t&1)*BUFB + KTB + lrow*(VSTR*2) + lcol;

        // ---- S = Q*K (single fp16 pass) ----
        float sa[8][4];
        #pragma unroll
        for (int j = 0; j < 8; j++){ sa[j][0]=0.f; sa[j][1]=0.f; sa[j][2]=0.f; sa[j][3]=0.f; }
        #pragma unroll
        for (int np = 0; np < 4; np++){
            #pragma unroll
            for (int kt = 0; kt < 9; kt++){
                uint32_t bb[4];
                ldsm4(bb, kmb + np*16*(KSTR*2) + kt*32);
                mma16816(sa[2*np],   &qh[4*kt], bb,   sa[2*np]);
                mma16816(sa[2*np+1], &qh[4*kt], bb+2, sa[2*np+1]);
            }
        }

        // ---- online softmax (log2 domain) ----
        float mx0 = -1e30f, mx1 = -1e30f;
        #pragma unroll
        for (int j = 0; j < 8; j++){
            mx0 = fmaxf(mx0, fmaxf(sa[j][0], sa[j][1]));
            mx1 = fmaxf(mx1, fmaxf(sa[j][2], sa[j][3]));
        }
        mx0 = fmaxf(mx0, __shfl_xor_sync(0xffffffffu, mx0, 1));
        mx0 = fmaxf(mx0, __shfl_xor_sync(0xffffffffu, mx0, 2));
        mx1 = fmaxf(mx1, __shfl_xor_sync(0xffffffffu, mx1, 1));
        mx1 = fmaxf(mx1, __shfl_xor_sync(0xffffffffu, mx1, 2));
        float m0n = fmaxf(m0, mx0), m1n = fmaxf(m1, mx1);
        float sc0 = ex2(m0 - m0n),  sc1 = ex2(m1 - m1n);
        m0 = m0n; m1 = m1n;
        float rs0 = 0.f, rs1 = 0.f;
        #pragma unroll
        for (int j = 0; j < 8; j++){
            sa[j][0] = ex2(sa[j][0] - m0); sa[j][1] = ex2(sa[j][1] - m0);
            sa[j][2] = ex2(sa[j][2] - m1); sa[j][3] = ex2(sa[j][3] - m1);
            rs0 += sa[j][0] + sa[j][1];
            rs1 += sa[j][2] + sa[j][3];
        }
        rs0 += __shfl_xor_sync(0xffffffffu, rs0, 1);
        rs0 += __shfl_xor_sync(0xffffffffu, rs0, 2);
        rs1 += __shfl_xor_sync(0xffffffffu, rs1, 1);
        rs1 += __shfl_xor_sync(0xffffffffu, rs1, 2);
        l0 = l0*sc0 + rs0;
        l1 = l1*sc1 + rs1;
        #pragma unroll
        for (int j = 0; j < 18; j++){
            oa[j][0] *= sc0; oa[j][1] *= sc0;
            oa[j][2] *= sc1; oa[j][3] *= sc1;
        }

        // ---- P fragments (A operand of PV) ----
        uint32_t pa[4][4];
        #pragma unroll
        for (int k2 = 0; k2 < 4; k2++){
            pa[k2][0] = pkh(sa[2*k2][0],   sa[2*k2][1]);
            pa[k2][1] = pkh(sa[2*k2][2],   sa[2*k2][3]);
            pa[k2][2] = pkh(sa[2*k2+1][0], sa[2*k2+1][1]);
            pa[k2][3] = pkh(sa[2*k2+1][2], sa[2*k2+1][3]);
        }

        // ---- O += P * V ----
        #pragma unroll
        for (int np = 0; np < 9; np++){
            #pragma unroll
            for (int k2 = 0; k2 < 4; k2++){
                uint32_t bb[4];
                ldsm4(bb, vmb + np*16*(VSTR*2) + k2*32);
                mma16816(oa[2*np],   pa[k2], bb,   oa[2*np]);
                mma16816(oa[2*np+1], pa[k2], bb+2, oa[2*np+1]);
            }
        }
        __syncthreads();
    }

    // ---- epilogue ----
    float i0 = 1.f/l0, i1 = 1.f/l1;
    if (row0 < NLOC){
        float* z = Zg + (size_t)row0*DH + tig*2;
        #pragma unroll
        for (int j = 0; j < 18; j++)
            *(float2*)(z + j*8) = make_float2(oa[j][0]*i0, oa[j][1]*i0);
    }
    if (row0 + 8 < NLOC){
        float* z = Zg + (size_t)(row0+8)*DH + tig*2;
        #pragma unroll
        for (int j = 0; j < 18; j++)
            *(float2*)(z + j*8) = make_float2(oa[j][2]*i1, oa[j][3]*i1);
    }
}

// ================= K4: fold + W conv + residual add, writes d_out directly ========
__global__ void fold_w_out_kernel(const float* __restrict__ Ww, const float* __restrict__ Wb,
                                  const float* __restrict__ bin, float* __restrict__ out)
{
    __shared__ float ws[CIN*CI];
    __shared__ float wb[CIN];
    int tid = threadIdx.x;
    for (int i = tid; i < CIN*CI; i += 256) ws[i] = Ww[i];
    if (tid < CIN) wb[tid] = Wb[tid];
    __syncthreads();

    int pix = blockIdx.x*256 + tid;
    int batch = blockIdx.y;
    int h = pix / 160, w = pix % 160;

    int krs[2], ihs[2], nr = 0;
    if (!(h & 1)){ krs[0] = 1; ihs[0] = h >> 1; nr = 1; }
    else { if (h < 159){ krs[nr] = 0; ihs[nr] = (h+1) >> 1; nr++; } krs[nr] = 2; ihs[nr] = (h-1) >> 1; nr++; }
    int kcs[2], iws[2], nc = 0;
    if (!(w & 1)){ kcs[0] = 1; iws[0] = w >> 1; nc = 1; }
    else { if (w < 159){ kcs[nc] = 0; iws[nc] = (w+1) >> 1; nc++; } kcs[nc] = 2; iws[nc] = (w-1) >> 1; nc++; }

    const float* Z = g_Z + (size_t)batch*NLOC*DH;
    float acc[CI];
    #pragma unroll
    for (int ci = 0; ci < CI; ci++) acc[ci] = 0.f;
    for (int a = 0; a < nr; a++)
        for (int bb = 0; bb < nc; bb++){
            int l = ihs[a]*80 + iws[bb];
            const float* zp = Z + (size_t)l*DH + krs[a]*3 + kcs[bb];
            #pragma unroll
            for (int ci = 0; ci < CI; ci++) acc[ci] += zp[ci*9];
        }
    float inv = 1.f / (float)(nr*nc);
    #pragma unroll
    for (int ci = 0; ci < CI; ci++) acc[ci] *= inv;

    const float* bp = bin + (size_t)batch*CIN*DD*NPIX + pix;
    float*       op = out + (size_t)batch*CIN*DD*NPIX + pix;
    #pragma unroll 2
    for (int c = 0; c < CIN; c++){
        float y = wb[c];
        #pragma unroll
        for (int ci = 0; ci < CI; ci++) y += ws[c*CI + ci]*acc[ci];
        const float* bc = bp + (size_t)c*DD*NPIX;
        float*       oc = op + (size_t)c*DD*NPIX;
        #pragma unroll
        for (int d = 0; d < DD; d++)
            oc[(size_t)d*NPIX] = bc[(size_t)d*NPIX] + y;
    }
}

// ================= launch =================
extern "C" void kernel_launch(void* const* d_in, const int* in_sizes, int n_in,
                              void* d_out, int out_size)
{
    const float* b  = (const float*)d_in[0];
    const float* gw = (const float*)d_in[1];
    const float* gb = (const float*)d_in[2];
    const float* tw = (const float*)d_in[3];
    const float* tb = (const float*)d_in[4];
    const float* pw = (const float*)d_in[5];
    const float* pb = (const float*)d_in[6];
    const float* Ww = (const float*)d_in[7];
    const float* Wb = (const float*)d_in[8];
    float* out = (float*)d_out;

    cudaFuncSetAttribute(flash_kernel, cudaFuncAttributeMaxDynamicSharedMemorySize, SMB_FLASH);

    conv_mid_kernel<<<dim3(100, 2), 256>>>(b, gw, gb, tw, tb, pw, pb);
    build_patches_kernel<<<dim3(3600, 3, 2), 256>>>();
    flash_kernel<<<dim3(67, 2), 192, SMB_FLASH>>>();
    fold_w_out_kernel<<<dim3(100, 2), 256>>>(Ww, Wb, b, out);
}